// round 2
// baseline (speedup 1.0000x reference)
#include <cuda_runtime.h>
#include <cstdint>

// ===========================================================================
// GCN_40750649704955: 2-layer GCN
//   layer(x, W, b): g = dinv .* (x@W);  out[d] = dinv[d]*(g[d] + sum_{e:dst=d} g[src]) + b
//   out = gcn(relu(gcn(x, W1, b1)), W2, b2)
// ===========================================================================

#define NMAX 50000

// -------- scratch (device globals; no runtime allocation allowed) ----------
__device__ __align__(16) float g_deg [NMAX];
__device__ __align__(16) float g_dinv[NMAX];
__device__ __align__(16) float g_G1  [(size_t)NMAX * 128];  // scaled hidden layer1
__device__ __align__(16) float g_AGG1[(size_t)NMAX * 128];  // aggregation buffer layer1
__device__ __align__(16) float g_X2  [(size_t)NMAX * 128];  // relu output -> layer2 input
__device__ __align__(16) float g_G2  [(size_t)NMAX * 64];
__device__ __align__(16) float g_AGG2[(size_t)NMAX * 64];

// ---------------------------------------------------------------------------
// degree / dinv
// ---------------------------------------------------------------------------
__global__ void init_deg_kernel(int n) {
    int i = blockIdx.x * blockDim.x + threadIdx.x;
    if (i < n) g_deg[i] = 1.0f;  // self-loop
}

__global__ void count_deg_kernel(const int* __restrict__ dst, int E) {
    int e = blockIdx.x * blockDim.x + threadIdx.x;
    if (e < E) atomicAdd(&g_deg[dst[e]], 1.0f);
}

__global__ void dinv_kernel(int n) {
    int i = blockIdx.x * blockDim.x + threadIdx.x;
    if (i < n) {
        float d = g_deg[i];
        g_dinv[i] = (d > 0.0f) ? rsqrtf(d) : 0.0f;
    }
}

// ---------------------------------------------------------------------------
// GEMM + row scale: G = dinv[row] * (X @ W);  AGG = G (self-loop init)
// BM=64 rows/block, K=128 fixed, BK=32, 256 threads (16x16), thread tile 4xTN
// ---------------------------------------------------------------------------
template <int N, int TN>
__global__ __launch_bounds__(256) void gemm_scale_kernel(
    const float* __restrict__ Xin, const float* __restrict__ W, int nrows)
{
    const float* X   = (N == 128) ? Xin    : g_X2;
    float*       G   = (N == 128) ? g_G1   : g_G2;
    float*       AGG = (N == 128) ? g_AGG1 : g_AGG2;

    __shared__ float Xs[64][36];   // 36 pad: keeps 16B alignment, shifts banks
    __shared__ float Ws[32][N];

    const int t  = threadIdx.x;
    const int tx = t & 15;
    const int ty = t >> 4;
    const int row0 = blockIdx.x * 64;

    float acc[4][TN];
#pragma unroll
    for (int r = 0; r < 4; r++)
#pragma unroll
        for (int c = 0; c < TN; c++) acc[r][c] = 0.0f;

    for (int k0 = 0; k0 < 128; k0 += 32) {
        // load X tile: 64x32 = 512 float4, 2 per thread
#pragma unroll
        for (int i = 0; i < 2; i++) {
            int idx = t + i * 256;
            int r   = idx >> 3;
            int c4  = (idx & 7) << 2;
            float4 v = make_float4(0.f, 0.f, 0.f, 0.f);
            int row = row0 + r;
            if (row < nrows)
                v = *reinterpret_cast<const float4*>(X + (size_t)row * 128 + k0 + c4);
            Xs[r][c4 + 0] = v.x; Xs[r][c4 + 1] = v.y;
            Xs[r][c4 + 2] = v.z; Xs[r][c4 + 3] = v.w;
        }
        // load W tile: 32xN floats, N/32 float4 per thread
#pragma unroll
        for (int i = 0; i < N / 32; i++) {
            int idx = t + i * 256;
            int r   = idx / (N / 4);
            int c4  = (idx % (N / 4)) << 2;
            float4 v = *reinterpret_cast<const float4*>(W + (size_t)(k0 + r) * N + c4);
            Ws[r][c4 + 0] = v.x; Ws[r][c4 + 1] = v.y;
            Ws[r][c4 + 2] = v.z; Ws[r][c4 + 3] = v.w;
        }
        __syncthreads();

#pragma unroll
        for (int kk = 0; kk < 32; kk++) {
            float a[4], b[TN];
#pragma unroll
            for (int r = 0; r < 4; r++) a[r] = Xs[ty * 4 + r][kk];
#pragma unroll
            for (int c = 0; c < TN; c++) b[c] = Ws[kk][tx * TN + c];
#pragma unroll
            for (int r = 0; r < 4; r++)
#pragma unroll
                for (int c = 0; c < TN; c++) acc[r][c] += a[r] * b[c];
        }
        __syncthreads();
    }

    // epilogue: scale by dinv[row], write G and AGG (self-loop contribution)
#pragma unroll
    for (int r = 0; r < 4; r++) {
        int row = row0 + ty * 4 + r;
        if (row >= nrows) continue;
        float s = g_dinv[row];
#pragma unroll
        for (int c4 = 0; c4 < TN; c4 += 4) {
            int col = tx * TN + c4;
            float4 v = make_float4(acc[r][c4 + 0] * s, acc[r][c4 + 1] * s,
                                   acc[r][c4 + 2] * s, acc[r][c4 + 3] * s);
            *reinterpret_cast<float4*>(G   + (size_t)row * N + col) = v;
            *reinterpret_cast<float4*>(AGG + (size_t)row * N + col) = v;
        }
    }
}

// ---------------------------------------------------------------------------
// edge scatter: AGG[dst] += G[src], vector f32x4 reductions
// layer1: 128 floats/row -> 1 warp per edge (32 lanes x float4)
// ---------------------------------------------------------------------------
__device__ __forceinline__ void red_add_v4(float* p, float4 v) {
    asm volatile("red.global.add.v4.f32 [%0], {%1, %2, %3, %4};"
                 :: "l"(p), "f"(v.x), "f"(v.y), "f"(v.z), "f"(v.w)
                 : "memory");
}

__global__ __launch_bounds__(256) void scatter128_kernel(
    const int* __restrict__ src, const int* __restrict__ dst, int E)
{
    int g = blockIdx.x * blockDim.x + threadIdx.x;
    int e = g >> 5;
    if (e >= E) return;
    int lane = g & 31;
    int s = __ldg(src + e);
    int d = __ldg(dst + e);
    float4 v = *reinterpret_cast<const float4*>(g_G1 + (size_t)s * 128 + lane * 4);
    red_add_v4(g_AGG1 + (size_t)d * 128 + lane * 4, v);
}

// layer2: 64 floats/row -> 16 lanes per edge
__global__ __launch_bounds__(256) void scatter64_kernel(
    const int* __restrict__ src, const int* __restrict__ dst, int E)
{
    int g = blockIdx.x * blockDim.x + threadIdx.x;
    int e = g >> 4;
    if (e >= E) return;
    int lane = g & 15;
    int s = __ldg(src + e);
    int d = __ldg(dst + e);
    float4 v = *reinterpret_cast<const float4*>(g_G2 + (size_t)s * 64 + lane * 4);
    red_add_v4(g_AGG2 + (size_t)d * 64 + lane * 4, v);
}

// ---------------------------------------------------------------------------
// epilogues
// ---------------------------------------------------------------------------
__global__ void finalize_relu_kernel(const float* __restrict__ b1, int nrows) {
    int idx = blockIdx.x * blockDim.x + threadIdx.x;       // float4 index
    int total = nrows * 32;                                 // 128/4 per row
    if (idx >= total) return;
    int row = idx >> 5;
    int c   = idx & 31;
    float  s  = g_dinv[row];
    float4 a  = reinterpret_cast<const float4*>(g_AGG1)[idx];
    float4 bb = reinterpret_cast<const float4*>(b1)[c];
    float4 v;
    v.x = fmaxf(s * a.x + bb.x, 0.0f);
    v.y = fmaxf(s * a.y + bb.y, 0.0f);
    v.z = fmaxf(s * a.z + bb.z, 0.0f);
    v.w = fmaxf(s * a.w + bb.w, 0.0f);
    reinterpret_cast<float4*>(g_X2)[idx] = v;
}

__global__ void finalize_out_kernel(float* __restrict__ out,
                                    const float* __restrict__ b2, int nrows) {
    int idx = blockIdx.x * blockDim.x + threadIdx.x;       // float4 index
    int total = nrows * 16;                                 // 64/4 per row
    if (idx >= total) return;
    int row = idx >> 4;
    int c   = idx & 15;
    float  s  = g_dinv[row];
    float4 a  = reinterpret_cast<const float4*>(g_AGG2)[idx];
    float4 bb = reinterpret_cast<const float4*>(b2)[c];
    float4 v;
    v.x = s * a.x + bb.x;
    v.y = s * a.y + bb.y;
    v.z = s * a.z + bb.z;
    v.w = s * a.w + bb.w;
    reinterpret_cast<float4*>(out)[idx] = v;
}

// ---------------------------------------------------------------------------
// launch
// ---------------------------------------------------------------------------
extern "C" void kernel_launch(void* const* d_in, const int* in_sizes, int n_in,
                              void* d_out, int out_size)
{
    const float* x  = (const float*)d_in[0];
    const int*   ei = (const int*)  d_in[1];
    const float* W1 = (const float*)d_in[2];
    const float* b1 = (const float*)d_in[3];
    const float* W2 = (const float*)d_in[4];
    const float* b2 = (const float*)d_in[5];

    const int nrows = in_sizes[0] / 128;   // 50000
    const int E     = in_sizes[1] / 2;     // 625000
    const int* src = ei;
    const int* dst = ei + E;

    // degree + dinv (graph-only; once per launch)
    init_deg_kernel<<<(nrows + 255) / 256, 256>>>(nrows);
    count_deg_kernel<<<(E + 255) / 256, 256>>>(dst, E);
    dinv_kernel<<<(nrows + 255) / 256, 256>>>(nrows);

    const int gemm_blocks = (nrows + 63) / 64;

    // ---- layer 1 ----
    gemm_scale_kernel<128, 8><<<gemm_blocks, 256>>>(x, W1, nrows);
    {
        long long threads = (long long)E * 32;
        scatter128_kernel<<<(int)((threads + 255) / 256), 256>>>(src, dst, E);
    }
    finalize_relu_kernel<<<(nrows * 32 + 255) / 256, 256>>>(b1, nrows);

    // ---- layer 2 ----
    gemm_scale_kernel<64, 4><<<gemm_blocks, 256>>>(nullptr, W2, nrows);
    {
        long long threads = (long long)E * 16;
        scatter64_kernel<<<(int)((threads + 255) / 256), 256>>>(src, dst, E);
    }
    finalize_out_kernel<<<(nrows * 16 + 255) / 256, 256>>>((float*)d_out, b2, nrows);
}

// round 6
// speedup vs baseline: 1.1433x; 1.1433x over previous
#include <cuda_runtime.h>
#include <cuda_bf16.h>
#include <cstdint>

// ===========================================================================
// GCN_40750649704955: 2-layer GCN
//   HMMA (mma.sync bf16, 3-pass split) GEMM + RED.v4 scatter
// ===========================================================================

#define NMAX 50000

__device__ __align__(16) float g_deg [NMAX];
__device__ __align__(16) float g_dinv[NMAX];
__device__ __align__(16) float g_G1  [(size_t)NMAX * 128];
__device__ __align__(16) float g_AGG1[(size_t)NMAX * 128];
__device__ __align__(16) float g_X2  [(size_t)NMAX * 128];
__device__ __align__(16) float g_G2  [(size_t)NMAX * 64];
__device__ __align__(16) float g_AGG2[(size_t)NMAX * 64];

// --------------------------- helpers ---------------------------------------
__device__ __forceinline__ uint32_t smem_u32(const void* p) {
    uint32_t a;
    asm("{ .reg .u64 t; cvta.to.shared.u64 t, %1; cvt.u32.u64 %0, t; }"
        : "=r"(a) : "l"(p));
    return a;
}

#define LDSM_X4(r0, r1, r2, r3, addr) \
    asm volatile("ldmatrix.sync.aligned.m8n8.x4.shared.b16 {%0,%1,%2,%3}, [%4];" \
                 : "=r"(r0), "=r"(r1), "=r"(r2), "=r"(r3) : "r"(addr))

#define LDSM_X4_T(r0, r1, r2, r3, addr) \
    asm volatile("ldmatrix.sync.aligned.m8n8.x4.trans.shared.b16 {%0,%1,%2,%3}, [%4];" \
                 : "=r"(r0), "=r"(r1), "=r"(r2), "=r"(r3) : "r"(addr))

__device__ __forceinline__ void mma_bf16(float* c, const uint32_t* a,
                                         uint32_t b0, uint32_t b1) {
    asm volatile(
        "mma.sync.aligned.m16n8k16.row.col.f32.bf16.bf16.f32 "
        "{%0,%1,%2,%3}, {%4,%5,%6,%7}, {%8,%9}, {%0,%1,%2,%3};"
        : "+f"(c[0]), "+f"(c[1]), "+f"(c[2]), "+f"(c[3])
        : "r"(a[0]), "r"(a[1]), "r"(a[2]), "r"(a[3]), "r"(b0), "r"(b1));
}

// ---------------------------------------------------------------------------
// degree / dinv
// ---------------------------------------------------------------------------
__global__ void init_deg_kernel(int n) {
    int i = blockIdx.x * blockDim.x + threadIdx.x;
    if (i < n) g_deg[i] = 1.0f;
}
__global__ void count_deg_kernel(const int* __restrict__ dst, int E) {
    int e = blockIdx.x * blockDim.x + threadIdx.x;
    if (e < E) atomicAdd(&g_deg[dst[e]], 1.0f);
}
__global__ void dinv_kernel(int n) {
    int i = blockIdx.x * blockDim.x + threadIdx.x;
    if (i < n) {
        float d = g_deg[i];
        g_dinv[i] = (d > 0.0f) ? rsqrtf(d) : 0.0f;
    }
}

// ---------------------------------------------------------------------------
// HMMA GEMM: G = dinv[row] .* (X @ W);  AGG = G   (self-loop init)
// CTA = 128 rows x N cols, K = 128. 8 warps, warp w -> rows [w*16, w*16+16).
// bf16 3-pass split: Ahi*Bhi + Ahi*Blo + Alo*Bhi in fp32 accumulators.
// SMEM: A[128][136] bf16 (hi,lo), B[k=128][N+8] bf16 (hi,lo); +8 pad makes
// every ldmatrix 8-lane phase hit 32 distinct banks.
// ---------------------------------------------------------------------------
template <int N>
__global__ __launch_bounds__(256, 1) void gemm_mma_kernel(
    const float* __restrict__ Xin, const float* __restrict__ W, int nrows)
{
    extern __shared__ char smem[];
    const float* X   = (N == 128) ? Xin    : g_X2;
    float*       G   = (N == 128) ? g_G1   : g_G2;
    float*       AGG = (N == 128) ? g_AGG1 : g_AGG2;

    constexpr int SA = 136;              // A row stride (bf16)
    constexpr int SB = N + 8;            // B row stride (bf16)
    constexpr int A_BYTES = 128 * SA * 2;    // 34816
    constexpr int B_BYTES = 128 * SB * 2;
    constexpr int A_HI = 0;
    constexpr int A_LO = A_HI + A_BYTES;
    constexpr int B_HI = A_LO + A_BYTES;
    constexpr int B_LO = B_HI + B_BYTES;
    constexpr int NT   = N / 8;          // n-tiles of 8 cols

    const int tid  = threadIdx.x;
    const int wid  = tid >> 5;
    const int lane = tid & 31;
    const int row0 = blockIdx.x * 128;

    // ---- stage A: 128 x 128 fp32 -> bf16 hi/lo (padded layout) ----
    for (int i = tid; i < 128 * 32; i += 256) {
        int r  = i >> 5;
        int c4 = i & 31;
        float4 v = make_float4(0.f, 0.f, 0.f, 0.f);
        int row = row0 + r;
        if (row < nrows) v = *(const float4*)(X + (size_t)row * 128 + c4 * 4);

        __nv_bfloat16 hx = __float2bfloat16(v.x), hy = __float2bfloat16(v.y);
        __nv_bfloat16 hz = __float2bfloat16(v.z), hw = __float2bfloat16(v.w);
        __nv_bfloat16 lx = __float2bfloat16(v.x - __bfloat162float(hx));
        __nv_bfloat16 ly = __float2bfloat16(v.y - __bfloat162float(hy));
        __nv_bfloat16 lz = __float2bfloat16(v.z - __bfloat162float(hz));
        __nv_bfloat16 lw = __float2bfloat16(v.w - __bfloat162float(hw));

        uint2 h = make_uint2(
            (uint32_t)__bfloat16_as_ushort(hx) | ((uint32_t)__bfloat16_as_ushort(hy) << 16),
            (uint32_t)__bfloat16_as_ushort(hz) | ((uint32_t)__bfloat16_as_ushort(hw) << 16));
        uint2 l = make_uint2(
            (uint32_t)__bfloat16_as_ushort(lx) | ((uint32_t)__bfloat16_as_ushort(ly) << 16),
            (uint32_t)__bfloat16_as_ushort(lz) | ((uint32_t)__bfloat16_as_ushort(lw) << 16));

        int off = (r * SA + c4 * 4) * 2;
        *(uint2*)(smem + A_HI + off) = h;
        *(uint2*)(smem + A_LO + off) = l;
    }

    // ---- stage B: W[128][N] fp32 -> bf16 hi/lo (already k-major rows) ----
    for (int i = tid; i < 128 * (N / 4); i += 256) {
        int k  = i / (N / 4);
        int nq = i % (N / 4);
        float4 v = *(const float4*)(W + (size_t)k * N + nq * 4);

        __nv_bfloat16 hx = __float2bfloat16(v.x), hy = __float2bfloat16(v.y);
        __nv_bfloat16 hz = __float2bfloat16(v.z), hw = __float2bfloat16(v.w);
        __nv_bfloat16 lx = __float2bfloat16(v.x - __bfloat162float(hx));
        __nv_bfloat16 ly = __float2bfloat16(v.y - __bfloat162float(hy));
        __nv_bfloat16 lz = __float2bfloat16(v.z - __bfloat162float(hz));
        __nv_bfloat16 lw = __float2bfloat16(v.w - __bfloat162float(hw));

        uint2 h = make_uint2(
            (uint32_t)__bfloat16_as_ushort(hx) | ((uint32_t)__bfloat16_as_ushort(hy) << 16),
            (uint32_t)__bfloat16_as_ushort(hz) | ((uint32_t)__bfloat16_as_ushort(hw) << 16));
        uint2 l = make_uint2(
            (uint32_t)__bfloat16_as_ushort(lx) | ((uint32_t)__bfloat16_as_ushort(ly) << 16),
            (uint32_t)__bfloat16_as_ushort(lz) | ((uint32_t)__bfloat16_as_ushort(lw) << 16));

        int off = (k * SB + nq * 4) * 2;
        *(uint2*)(smem + B_HI + off) = h;
        *(uint2*)(smem + B_LO + off) = l;
    }
    __syncthreads();

    // ---- compute ----
    const uint32_t sb = smem_u32(smem);
    float cfrag[NT][4];
#pragma unroll
    for (int t = 0; t < NT; t++)
#pragma unroll
        for (int j = 0; j < 4; j++) cfrag[t][j] = 0.0f;

    // ldmatrix lane addressing (byte offsets)
    const uint32_t aAddr = sb + (uint32_t)(((wid * 16 + (lane & 15)) * SA
                                            + (lane >> 4) * 8) * 2);
    const uint32_t bAddr = sb + B_HI + (uint32_t)(((lane & 15) * SB
                                            + (lane >> 4) * 8) * 2);

#pragma unroll
    for (int ks = 0; ks < 8; ks++) {
        uint32_t ah[4], al[4];
        LDSM_X4(ah[0], ah[1], ah[2], ah[3], aAddr + ks * 32);
        LDSM_X4(al[0], al[1], al[2], al[3], aAddr + A_LO + ks * 32);

#pragma unroll
        for (int ng = 0; ng < N / 16; ng++) {
            uint32_t bh[4], bl[4];
            uint32_t bo = bAddr + (uint32_t)(ks * 16 * SB * 2 + ng * 32);
            LDSM_X4_T(bh[0], bh[1], bh[2], bh[3], bo);
            LDSM_X4_T(bl[0], bl[1], bl[2], bl[3], bo + B_BYTES);

            mma_bf16(cfrag[2 * ng],     ah, bh[0], bh[1]);
            mma_bf16(cfrag[2 * ng + 1], ah, bh[2], bh[3]);
            mma_bf16(cfrag[2 * ng],     ah, bl[0], bl[1]);
            mma_bf16(cfrag[2 * ng + 1], ah, bl[2], bl[3]);
            mma_bf16(cfrag[2 * ng],     al, bh[0], bh[1]);
            mma_bf16(cfrag[2 * ng + 1], al, bh[2], bh[3]);
        }
    }

    // ---- epilogue: scale by dinv, write G + AGG ----
    {
        const int rA = row0 + wid * 16 + (lane >> 2);     // rows l>>2 and +8
        const int rB = rA + 8;
        const int c0 = (lane & 3) * 2;
        float sA = (rA < nrows) ? g_dinv[rA] : 0.0f;
        float sB = (rB < nrows) ? g_dinv[rB] : 0.0f;
#pragma unroll
        for (int t = 0; t < NT; t++) {
            int col = t * 8 + c0;
            if (rA < nrows) {
                float2 v = make_float2(cfrag[t][0] * sA, cfrag[t][1] * sA);
                size_t off = (size_t)rA * N + col;
                *(float2*)(G + off)   = v;
                *(float2*)(AGG + off) = v;
            }
            if (rB < nrows) {
                float2 v = make_float2(cfrag[t][2] * sB, cfrag[t][3] * sB);
                size_t off = (size_t)rB * N + col;
                *(float2*)(G + off)   = v;
                *(float2*)(AGG + off) = v;
            }
        }
    }
}

// ---------------------------------------------------------------------------
// edge scatter: AGG[dst] += G[src], vector f32x4 reductions
// ---------------------------------------------------------------------------
__device__ __forceinline__ void red_add_v4(float* p, float4 v) {
    asm volatile("red.global.add.v4.f32 [%0], {%1, %2, %3, %4};"
                 :: "l"(p), "f"(v.x), "f"(v.y), "f"(v.z), "f"(v.w)
                 : "memory");
}

__global__ __launch_bounds__(256) void scatter128_kernel(
    const int* __restrict__ src, const int* __restrict__ dst, int E)
{
    int g = blockIdx.x * blockDim.x + threadIdx.x;
    int e = g >> 5;
    if (e >= E) return;
    int lane = g & 31;
    int s = __ldg(src + e);
    int d = __ldg(dst + e);
    float4 v = *reinterpret_cast<const float4*>(g_G1 + (size_t)s * 128 + lane * 4);
    red_add_v4(g_AGG1 + (size_t)d * 128 + lane * 4, v);
}

__global__ __launch_bounds__(256) void scatter64_kernel(
    const int* __restrict__ src, const int* __restrict__ dst, int E)
{
    int g = blockIdx.x * blockDim.x + threadIdx.x;
    int e = g >> 4;
    if (e >= E) return;
    int lane = g & 15;
    int s = __ldg(src + e);
    int d = __ldg(dst + e);
    float4 v = *reinterpret_cast<const float4*>(g_G2 + (size_t)s * 64 + lane * 4);
    red_add_v4(g_AGG2 + (size_t)d * 64 + lane * 4, v);
}

// ---------------------------------------------------------------------------
// epilogues
// ---------------------------------------------------------------------------
__global__ void finalize_relu_kernel(const float* __restrict__ b1, int nrows) {
    int idx = blockIdx.x * blockDim.x + threadIdx.x;
    int total = nrows * 32;
    if (idx >= total) return;
    int row = idx >> 5;
    int c   = idx & 31;
    float  s  = g_dinv[row];
    float4 a  = reinterpret_cast<const float4*>(g_AGG1)[idx];
    float4 bb = reinterpret_cast<const float4*>(b1)[c];
    float4 v;
    v.x = fmaxf(s * a.x + bb.x, 0.0f);
    v.y = fmaxf(s * a.y + bb.y, 0.0f);
    v.z = fmaxf(s * a.z + bb.z, 0.0f);
    v.w = fmaxf(s * a.w + bb.w, 0.0f);
    reinterpret_cast<float4*>(g_X2)[idx] = v;
}

__global__ void finalize_out_kernel(float* __restrict__ out,
                                    const float* __restrict__ b2, int nrows) {
    int idx = blockIdx.x * blockDim.x + threadIdx.x;
    int total = nrows * 16;
    if (idx >= total) return;
    int row = idx >> 4;
    int c   = idx & 15;
    float  s  = g_dinv[row];
    float4 a  = reinterpret_cast<const float4*>(g_AGG2)[idx];
    float4 bb = reinterpret_cast<const float4*>(b2)[c];
    float4 v;
    v.x = s * a.x + bb.x;
    v.y = s * a.y + bb.y;
    v.z = s * a.z + bb.z;
    v.w = s * a.w + bb.w;
    reinterpret_cast<float4*>(out)[idx] = v;
}

// ---------------------------------------------------------------------------
// launch
// ---------------------------------------------------------------------------
extern "C" void kernel_launch(void* const* d_in, const int* in_sizes, int n_in,
                              void* d_out, int out_size)
{
    const float* x  = (const float*)d_in[0];
    const int*   ei = (const int*)  d_in[1];
    const float* W1 = (const float*)d_in[2];
    const float* b1 = (const float*)d_in[3];
    const float* W2 = (const float*)d_in[4];
    const float* b2 = (const float*)d_in[5];

    const int nrows = in_sizes[0] / 128;   // 50000
    const int E     = in_sizes[1] / 2;     // 625000
    const int* src = ei;
    const int* dst = ei + E;

    constexpr int SMEM1 = 2 * (128 * 136 * 2) + 2 * (128 * 136 * 2);  // 139264
    constexpr int SMEM2 = 2 * (128 * 136 * 2) + 2 * (128 * 72 * 2);   // 106496
    cudaFuncSetAttribute(gemm_mma_kernel<128>,
                         cudaFuncAttributeMaxDynamicSharedMemorySize, SMEM1);
    cudaFuncSetAttribute(gemm_mma_kernel<64>,
                         cudaFuncAttributeMaxDynamicSharedMemorySize, SMEM2);

    init_deg_kernel<<<(nrows + 255) / 256, 256>>>(nrows);
    count_deg_kernel<<<(E + 255) / 256, 256>>>(dst, E);
    dinv_kernel<<<(nrows + 255) / 256, 256>>>(nrows);

    const int gemm_blocks = (nrows + 127) / 128;  // 391

    // ---- layer 1 ----
    gemm_mma_kernel<128><<<gemm_blocks, 256, SMEM1>>>(x, W1, nrows);
    {
        long long threads = (long long)E * 32;
        scatter128_kernel<<<(int)((threads + 255) / 256), 256>>>(src, dst, E);
    }
    finalize_relu_kernel<<<(nrows * 32 + 255) / 256, 256>>>(b1, nrows);

    // ---- layer 2 ----
    gemm_mma_kernel<64><<<gemm_blocks, 256, SMEM2>>>(nullptr, W2, nrows);
    {
        long long threads = (long long)E * 16;
        scatter64_kernel<<<(int)((threads + 255) / 256), 256>>>(src, dst, E);
    }
    finalize_out_kernel<<<(nrows * 16 + 255) / 256, 256>>>((float*)d_out, b2, nrows);
}

// round 9
// speedup vs baseline: 1.7117x; 1.4972x over previous
#include <cuda_runtime.h>
#include <cuda_bf16.h>
#include <cstdint>

// ===========================================================================
// GCN_40750649704955: 2-layer GCN
//   preconvert bf16 hi/lo -> cp.async (<=48KB) pipelined HMMA GEMM
//   -> CSR fused gather (no atomics in hot loop)
// NOTE: all __device__ globals are referenced from DEVICE code only
// (host-side &global is the shadow symbol -> garbage pointer).
// ===========================================================================

#define NMAX  50000
#define EMAX  700000

// -------- scratch ----------------------------------------------------------
__device__ __align__(16) int   g_cnt     [NMAX];
__device__ __align__(16) int   g_cursor  [NMAX];
__device__ __align__(16) int   g_rowstart[NMAX + 1];
__device__ __align__(16) int   g_col     [EMAX];
__device__ __align__(16) float g_dinv    [NMAX];

__device__ __align__(16) __nv_bfloat16 g_Xhi [(size_t)NMAX * 128];
__device__ __align__(16) __nv_bfloat16 g_Xlo [(size_t)NMAX * 128];
__device__ __align__(16) __nv_bfloat16 g_X2hi[(size_t)NMAX * 128];
__device__ __align__(16) __nv_bfloat16 g_X2lo[(size_t)NMAX * 128];
__device__ __align__(16) __nv_bfloat16 g_W1hi[128 * 128];
__device__ __align__(16) __nv_bfloat16 g_W1lo[128 * 128];
__device__ __align__(16) __nv_bfloat16 g_W2hi[128 * 64];
__device__ __align__(16) __nv_bfloat16 g_W2lo[128 * 64];

__device__ __align__(16) float g_G1[(size_t)NMAX * 128];
__device__ __align__(16) float g_G2[(size_t)NMAX * 64];

// --------------------------- asm helpers -----------------------------------
__device__ __forceinline__ uint32_t smem_u32(const void* p) {
    uint32_t a;
    asm("{ .reg .u64 t; cvta.to.shared.u64 t, %1; cvt.u32.u64 %0, t; }"
        : "=r"(a) : "l"(p));
    return a;
}
#define CP_ASYNC16(dst, src, sz) \
    asm volatile("cp.async.cg.shared.global [%0], [%1], 16, %2;" \
                 :: "r"(dst), "l"(src), "r"(sz) : "memory")
#define CP_COMMIT() asm volatile("cp.async.commit_group;" ::: "memory")
#define CP_WAIT0()  asm volatile("cp.async.wait_group 0;" ::: "memory")
#define CP_WAIT1()  asm volatile("cp.async.wait_group 1;" ::: "memory")

#define LDSM_X4(r0, r1, r2, r3, addr) \
    asm volatile("ldmatrix.sync.aligned.m8n8.x4.shared.b16 {%0,%1,%2,%3}, [%4];" \
                 : "=r"(r0), "=r"(r1), "=r"(r2), "=r"(r3) : "r"(addr))
#define LDSM_X4_T(r0, r1, r2, r3, addr) \
    asm volatile("ldmatrix.sync.aligned.m8n8.x4.trans.shared.b16 {%0,%1,%2,%3}, [%4];" \
                 : "=r"(r0), "=r"(r1), "=r"(r2), "=r"(r3) : "r"(addr))

__device__ __forceinline__ void mma_bf16(float* c, const uint32_t* a,
                                         uint32_t b0, uint32_t b1) {
    asm volatile(
        "mma.sync.aligned.m16n8k16.row.col.f32.bf16.bf16.f32 "
        "{%0,%1,%2,%3}, {%4,%5,%6,%7}, {%8,%9}, {%0,%1,%2,%3};"
        : "+f"(c[0]), "+f"(c[1]), "+f"(c[2]), "+f"(c[3])
        : "r"(a[0]), "r"(a[1]), "r"(a[2]), "r"(a[3]), "r"(b0), "r"(b1));
}

__device__ __forceinline__ void split_bf16(float v, __nv_bfloat16& h, __nv_bfloat16& l) {
    h = __float2bfloat16(v);
    l = __float2bfloat16(v - __bfloat162float(h));
}

// ---------------------------------------------------------------------------
// preconvert kernels
// ---------------------------------------------------------------------------
__global__ void zero_counts_kernel(int n) {
    int i = blockIdx.x * blockDim.x + threadIdx.x;
    if (i < n) { g_cnt[i] = 0; g_cursor[i] = 0; }
}

__global__ void conv_x_kernel(const float* __restrict__ X, int total4) {
    int i = blockIdx.x * blockDim.x + threadIdx.x;
    if (i >= total4) return;
    float4 v = reinterpret_cast<const float4*>(X)[i];
    __nv_bfloat16 hx, hy, hz, hw, lx, ly, lz, lw;
    split_bf16(v.x, hx, lx); split_bf16(v.y, hy, ly);
    split_bf16(v.z, hz, lz); split_bf16(v.w, hw, lw);
    uint2 h = make_uint2(
        (uint32_t)__bfloat16_as_ushort(hx) | ((uint32_t)__bfloat16_as_ushort(hy) << 16),
        (uint32_t)__bfloat16_as_ushort(hz) | ((uint32_t)__bfloat16_as_ushort(hw) << 16));
    uint2 l = make_uint2(
        (uint32_t)__bfloat16_as_ushort(lx) | ((uint32_t)__bfloat16_as_ushort(ly) << 16),
        (uint32_t)__bfloat16_as_ushort(lz) | ((uint32_t)__bfloat16_as_ushort(lw) << 16));
    reinterpret_cast<uint2*>(g_Xhi)[i] = h;
    reinterpret_cast<uint2*>(g_Xlo)[i] = l;
}

template <int N>
__global__ void conv_w_kernel(const float* __restrict__ W) {
    __nv_bfloat16* hi = (N == 128) ? g_W1hi : g_W2hi;
    __nv_bfloat16* lo = (N == 128) ? g_W1lo : g_W2lo;
    int i = blockIdx.x * blockDim.x + threadIdx.x;
    if (i < 128 * N) {
        __nv_bfloat16 h, l;
        split_bf16(W[i], h, l);
        hi[i] = h; lo[i] = l;
    }
}

// ---------------------------------------------------------------------------
// CSR build
// ---------------------------------------------------------------------------
__global__ void hist_kernel(const int* __restrict__ dst, int E) {
    int e = blockIdx.x * blockDim.x + threadIdx.x;
    if (e < E) atomicAdd(&g_cnt[dst[e]], 1);
}

__global__ void scan_kernel(int n) {   // single block, 1024 threads
    __shared__ int wsums[32];
    __shared__ int s_carry;
    int tid = threadIdx.x, lane = tid & 31, wid = tid >> 5;
    if (tid == 0) s_carry = 0;
    __syncthreads();
    for (int base = 0; base < n; base += 1024) {
        int i = base + tid;
        int v = (i < n) ? g_cnt[i] : 0;
        int x = v;
#pragma unroll
        for (int d = 1; d < 32; d <<= 1) {
            int y = __shfl_up_sync(0xffffffffu, x, d);
            if (lane >= d) x += y;
        }
        if (lane == 31) wsums[wid] = x;
        __syncthreads();
        if (wid == 0) {
            int s = wsums[lane];
#pragma unroll
            for (int d = 1; d < 32; d <<= 1) {
                int y = __shfl_up_sync(0xffffffffu, s, d);
                if (lane >= d) s += y;
            }
            wsums[lane] = s;
        }
        __syncthreads();
        int warpoff = (wid == 0) ? 0 : wsums[wid - 1];
        int excl = s_carry + warpoff + x - v;
        if (i < n) g_rowstart[i] = excl;
        int total = wsums[31];
        __syncthreads();
        if (tid == 0) s_carry += total;
        __syncthreads();
    }
    if (threadIdx.x == 0) g_rowstart[n] = s_carry;
}

__global__ void dinv_kernel(int n) {
    int i = blockIdx.x * blockDim.x + threadIdx.x;
    if (i < n) g_dinv[i] = rsqrtf((float)g_cnt[i] + 1.0f);   // +1 self-loop
}

__global__ void fill_kernel(const int* __restrict__ src,
                            const int* __restrict__ dst, int E) {
    int e = blockIdx.x * blockDim.x + threadIdx.x;
    if (e < E) {
        int d = dst[e];
        int p = g_rowstart[d] + atomicAdd(&g_cursor[d], 1);
        g_col[p] = src[e];
    }
}

// ---------------------------------------------------------------------------
// cp.async pipelined HMMA GEMM:  G = dinv[row] .* (A @ W)
// CTA 128 rows x N cols. 8 warps: warp = (wid&3)*32 rows x (wid>>2)*(N/2) cols.
// K=128 streamed as 8 chunks of k=16, double-buffered. 3-pass bf16 split.
// Globals selected DEVICE-SIDE via template parameter N.
// Smem: N=128 -> 41984 B, N=64 -> 33792 B  (<48KB: no opt-in attr).
// ---------------------------------------------------------------------------
template <int N>
__global__ __launch_bounds__(256, 2) void gemm_pipe_kernel(int nrows)
{
    extern __shared__ char smem[];
    const __nv_bfloat16* __restrict__ Ahi = (N == 128) ? g_Xhi  : g_X2hi;
    const __nv_bfloat16* __restrict__ Alo = (N == 128) ? g_Xlo  : g_X2lo;
    const __nv_bfloat16* __restrict__ Bhi = (N == 128) ? g_W1hi : g_W2hi;
    const __nv_bfloat16* __restrict__ Blo = (N == 128) ? g_W1lo : g_W2lo;
    float* __restrict__ G                 = (N == 128) ? g_G1   : g_G2;

    constexpr int SBb  = (N + 8) * 2;          // B row stride bytes (272 / 144)
    constexpr int AH_O = 0;
    constexpr int AL_O = 128 * 48;             // 6144
    constexpr int BH_O = 2 * 128 * 48;         // 12288
    constexpr int BSZ  = 16 * SBb;             // 4352 / 2304
    constexpr int BL_O = BH_O + BSZ;
    constexpr int BUF  = BH_O + 2 * BSZ;       // 20992 / 16896
    constexpr int BPR  = N / 8;                // 16B pieces per B row
    constexpr int BOPS = 16 * BPR * 2;         // 512 / 256
    constexpr int CW   = N / 2;                // warp col width
    constexpr int NG   = CW / 16;              // 4 / 2

    const int tid  = threadIdx.x;
    const int wid  = tid >> 5;
    const int lane = tid & 31;
    const int row0 = blockIdx.x * 128;
    const uint32_t sb = smem_u32(smem);

    // ---- cp.async issue for chunk c (k = c*16..c*16+15) into buffer (c&1) ----
    auto issue = [&](int c) {
        const uint32_t base = sb + (uint32_t)(c & 1) * BUF;
        // A: 512 ops (hi+lo), 2 x 16B per row
#pragma unroll
        for (int it = 0; it < 2; it++) {
            int i   = tid + it * 256;          // 0..511
            int mat = i >> 8;                  // 0=hi 1=lo
            int idx = i & 255;
            int r   = idx >> 1;                // 0..127
            int j   = idx & 1;                 // 0..1
            uint32_t dst = base + (mat ? AL_O : AH_O) + r * 48 + j * 16;
            const __nv_bfloat16* srcb = mat ? Alo : Ahi;
            int row = row0 + r;
            int srow = (row < nrows) ? row : 0;     // clamp: stay in-bounds
            const char* src = (const char*)srcb
                            + (size_t)srow * 256 + c * 32 + j * 16;
            uint32_t sz = (row < nrows) ? 16u : 0u;
            CP_ASYNC16(dst, src, sz);
        }
        // B: BOPS ops (hi+lo), 16 k-rows x BPR pieces
#pragma unroll
        for (int it = 0; it < BOPS / 256; it++) {
            int i   = tid + it * 256;
            int mat = i >= BOPS / 2;
            int idx = mat ? (i - BOPS / 2) : i;
            int r   = idx / BPR;               // 0..15
            int j   = idx % BPR;
            uint32_t dst = base + (mat ? BL_O : BH_O) + r * SBb + j * 16;
            const __nv_bfloat16* srcb = mat ? Blo : Bhi;
            const char* src = (const char*)srcb + (size_t)(c * 16 + r) * N * 2 + j * 16;
            CP_ASYNC16(dst, src, 16u);
        }
    };

    const int wrow = (wid & 3) * 32;
    const int col0 = (wid >> 2) * CW;

    float cfrag[2][CW / 8][4];
#pragma unroll
    for (int mi = 0; mi < 2; mi++)
#pragma unroll
        for (int t = 0; t < CW / 8; t++)
#pragma unroll
            for (int j = 0; j < 4; j++) cfrag[mi][t][j] = 0.0f;

    issue(0); CP_COMMIT();
    issue(1); CP_COMMIT();

    for (int c = 0; c < 8; c++) {
        if (c == 7) { CP_WAIT0(); } else { CP_WAIT1(); }
        __syncthreads();

        const uint32_t base = sb + (uint32_t)(c & 1) * BUF;
        uint32_t a0 = base + AH_O + (wrow + (lane & 15)) * 48 + (lane >> 4) * 16;
        uint32_t a1 = a0 + 16 * 48;
        uint32_t ah0[4], ah1[4], al0[4], al1[4];
        LDSM_X4(ah0[0], ah0[1], ah0[2], ah0[3], a0);
        LDSM_X4(ah1[0], ah1[1], ah1[2], ah1[3], a1);
        LDSM_X4(al0[0], al0[1], al0[2], al0[3], a0 + AL_O);
        LDSM_X4(al1[0], al1[1], al1[2], al1[3], a1 + AL_O);

#pragma unroll
        for (int ng = 0; ng < NG; ng++) {
            uint32_t bo = base + BH_O + (lane & 15) * SBb + (lane >> 4) * 16
                        + (col0 + ng * 16) * 2;
            uint32_t bh[4], bl[4];
            LDSM_X4_T(bh[0], bh[1], bh[2], bh[3], bo);
            LDSM_X4_T(bl[0], bl[1], bl[2], bl[3], bo + BSZ);

            mma_bf16(cfrag[0][2 * ng],     ah0, bh[0], bh[1]);
            mma_bf16(cfrag[0][2 * ng + 1], ah0, bh[2], bh[3]);
            mma_bf16(cfrag[1][2 * ng],     ah1, bh[0], bh[1]);
            mma_bf16(cfrag[1][2 * ng + 1], ah1, bh[2], bh[3]);
            mma_bf16(cfrag[0][2 * ng],     ah0, bl[0], bl[1]);
            mma_bf16(cfrag[0][2 * ng + 1], ah0, bl[2], bl[3]);
            mma_bf16(cfrag[1][2 * ng],     ah1, bl[0], bl[1]);
            mma_bf16(cfrag[1][2 * ng + 1], ah1, bl[2], bl[3]);
            mma_bf16(cfrag[0][2 * ng],     al0, bh[0], bh[1]);
            mma_bf16(cfrag[0][2 * ng + 1], al0, bh[2], bh[3]);
            mma_bf16(cfrag[1][2 * ng],     al1, bh[0], bh[1]);
            mma_bf16(cfrag[1][2 * ng + 1], al1, bh[2], bh[3]);
        }
        __syncthreads();
        if (c < 6) { issue(c + 2); CP_COMMIT(); }
    }

    // ---- epilogue: dinv scale, fp32 store ----
#pragma unroll
    for (int mi = 0; mi < 2; mi++) {
        int rA = row0 + wrow + mi * 16 + (lane >> 2);
        int rB = rA + 8;
        float sA = (rA < nrows) ? g_dinv[rA] : 0.0f;
        float sB = (rB < nrows) ? g_dinv[rB] : 0.0f;
#pragma unroll
        for (int t = 0; t < CW / 8; t++) {
            int col = col0 + t * 8 + (lane & 3) * 2;
            if (rA < nrows)
                *(float2*)(G + (size_t)rA * N + col) =
                    make_float2(cfrag[mi][t][0] * sA, cfrag[mi][t][1] * sA);
            if (rB < nrows)
                *(float2*)(G + (size_t)rB * N + col) =
                    make_float2(cfrag[mi][t][2] * sB, cfrag[mi][t][3] * sB);
        }
    }
}

// ---------------------------------------------------------------------------
// fused CSR gather + finalize
// layer 1: out = relu(dinv[d]*(G1[d] + sum G1[src]) + b1) -> X2hi/X2lo
// ---------------------------------------------------------------------------
__global__ __launch_bounds__(256) void gather1_kernel(
    const float* __restrict__ b1, int n)
{
    int wid  = threadIdx.x >> 5;
    int lane = threadIdx.x & 31;
    int row  = blockIdx.x * 8 + wid;
    if (row >= n) return;

    const float4* G = reinterpret_cast<const float4*>(g_G1);
    int s0 = g_rowstart[row], s1 = g_rowstart[row + 1];

    float4 acc  = G[(size_t)row * 32 + lane];          // self-loop term
    float4 acc2 = make_float4(0.f, 0.f, 0.f, 0.f);
    int e = s0;
    for (; e + 2 <= s1; e += 2) {
        int a = g_col[e], b = g_col[e + 1];
        float4 va = G[(size_t)a * 32 + lane];
        float4 vb = G[(size_t)b * 32 + lane];
        acc.x += va.x;  acc.y += va.y;  acc.z += va.z;  acc.w += va.w;
        acc2.x += vb.x; acc2.y += vb.y; acc2.z += vb.z; acc2.w += vb.w;
    }
    if (e < s1) {
        float4 va = G[(size_t)g_col[e] * 32 + lane];
        acc.x += va.x; acc.y += va.y; acc.z += va.z; acc.w += va.w;
    }
    acc.x += acc2.x; acc.y += acc2.y; acc.z += acc2.z; acc.w += acc2.w;

    float sc = g_dinv[row];
    float4 bv = reinterpret_cast<const float4*>(b1)[lane];
    float vx = fmaxf(sc * acc.x + bv.x, 0.0f);
    float vy = fmaxf(sc * acc.y + bv.y, 0.0f);
    float vz = fmaxf(sc * acc.z + bv.z, 0.0f);
    float vw = fmaxf(sc * acc.w + bv.w, 0.0f);

    __nv_bfloat16 hx, hy, hz, hw, lx, ly, lz, lw;
    split_bf16(vx, hx, lx); split_bf16(vy, hy, ly);
    split_bf16(vz, hz, lz); split_bf16(vw, hw, lw);
    uint2 h = make_uint2(
        (uint32_t)__bfloat16_as_ushort(hx) | ((uint32_t)__bfloat16_as_ushort(hy) << 16),
        (uint32_t)__bfloat16_as_ushort(hz) | ((uint32_t)__bfloat16_as_ushort(hw) << 16));
    uint2 l = make_uint2(
        (uint32_t)__bfloat16_as_ushort(lx) | ((uint32_t)__bfloat16_as_ushort(ly) << 16),
        (uint32_t)__bfloat16_as_ushort(lz) | ((uint32_t)__bfloat16_as_ushort(lw) << 16));
    size_t oi = (size_t)row * 32 + lane;
    reinterpret_cast<uint2*>(g_X2hi)[oi] = h;
    reinterpret_cast<uint2*>(g_X2lo)[oi] = l;
}

// layer 2: out = dinv[d]*(G2[d] + sum G2[src]) + b2   (fp32, no relu)
__global__ __launch_bounds__(256) void gather2_kernel(
    float* __restrict__ out, const float* __restrict__ b2, int n)
{
    int wid  = threadIdx.x >> 5;
    int lane = threadIdx.x & 31;
    int row  = blockIdx.x * 8 + wid;
    if (row >= n) return;

    const float2* G = reinterpret_cast<const float2*>(g_G2);
    int s0 = g_rowstart[row], s1 = g_rowstart[row + 1];

    float2 acc  = G[(size_t)row * 32 + lane];
    float2 acc2 = make_float2(0.f, 0.f);
    int e = s0;
    for (; e + 2 <= s1; e += 2) {
        int a = g_col[e], b = g_col[e + 1];
        float2 va = G[(size_t)a * 32 + lane];
        float2 vb = G[(size_t)b * 32 + lane];
        acc.x += va.x;  acc.y += va.y;
        acc2.x += vb.x; acc2.y += vb.y;
    }
    if (e < s1) {
        float2 va = G[(size_t)g_col[e] * 32 + lane];
        acc.x += va.x; acc.y += va.y;
    }
    acc.x += acc2.x; acc.y += acc2.y;

    float sc = g_dinv[row];
    float2 bv = reinterpret_cast<const float2*>(b2)[lane];
    reinterpret_cast<float2*>(out)[(size_t)row * 32 + lane] =
        make_float2(sc * acc.x + bv.x, sc * acc.y + bv.y);
}

// ---------------------------------------------------------------------------
// launch
// ---------------------------------------------------------------------------
extern "C" void kernel_launch(void* const* d_in, const int* in_sizes, int n_in,
                              void* d_out, int out_size)
{
    const float* x  = (const float*)d_in[0];
    const int*   ei = (const int*)  d_in[1];
    const float* W1 = (const float*)d_in[2];
    const float* b1 = (const float*)d_in[3];
    const float* W2 = (const float*)d_in[4];
    const float* b2 = (const float*)d_in[5];

    const int nrows = in_sizes[0] / 128;   // 50000
    const int E     = in_sizes[1] / 2;     // 625000
    const int* src = ei;
    const int* dst = ei + E;

    // per-CTA dynamic smem (both < 48KB -> no cudaFuncSetAttribute needed)
    constexpr int SMEM128 = 2 * (2 * 128 * 48 + 2 * 16 * (128 + 8) * 2);  // 41984
    constexpr int SMEM64  = 2 * (2 * 128 * 48 + 2 * 16 * (64 + 8) * 2);   // 33792

    // preconvert + CSR build
    zero_counts_kernel<<<(nrows + 255) / 256, 256>>>(nrows);
    conv_x_kernel<<<(nrows * 32 + 255) / 256, 256>>>(x, nrows * 32);
    conv_w_kernel<128><<<(128 * 128 + 255) / 256, 256>>>(W1);
    conv_w_kernel<64><<<(128 * 64 + 255) / 256, 256>>>(W2);
    hist_kernel<<<(E + 255) / 256, 256>>>(dst, E);
    scan_kernel<<<1, 1024>>>(nrows);
    dinv_kernel<<<(nrows + 255) / 256, 256>>>(nrows);
    fill_kernel<<<(E + 255) / 256, 256>>>(src, dst, E);

    const int gemm_blocks   = (nrows + 127) / 128;  // 391
    const int gather_blocks = (nrows + 7) / 8;      // 6250

    // ---- layer 1 ----
    gemm_pipe_kernel<128><<<gemm_blocks, 256, SMEM128>>>(nrows);
    gather1_kernel<<<gather_blocks, 256>>>(b1, nrows);

    // ---- layer 2 ----
    gemm_pipe_kernel<64><<<gemm_blocks, 256, SMEM64>>>(nrows);
    gather2_kernel<<<gather_blocks, 256>>>((float*)d_out, b2, nrows);
}

// round 10
// speedup vs baseline: 2.2572x; 1.3187x over previous
#include <cuda_runtime.h>
#include <cuda_bf16.h>
#include <cuda_fp16.h>
#include <cstdint>

// ===========================================================================
// GCN_40750649704955: 2-layer GCN
//   fused preconvert -> parallel-scan CSR -> cp.async HMMA GEMM -> fused gather
//   G1 stored fp16 (halves gather1 L2 traffic); G2 fp32 (feeds output).
// All __device__ globals referenced from DEVICE code only.
// ===========================================================================

#define NMAX  50000
#define EMAX  700000
#define NBLK  ((NMAX + 1023) / 1024)   // 49 scan blocks

// -------- scratch ----------------------------------------------------------
__device__ __align__(16) int   g_cnt     [NMAX];
__device__ __align__(16) int   g_cursor  [NMAX];
__device__ __align__(16) int   g_rowstart[NMAX + 1];
__device__ __align__(16) int   g_btot    [NBLK];
__device__ __align__(16) int   g_boff    [NBLK];
__device__ __align__(16) int   g_col     [EMAX];
__device__ __align__(16) float g_dinv    [NMAX];

__device__ __align__(16) __nv_bfloat16 g_Xhi [(size_t)NMAX * 128];
__device__ __align__(16) __nv_bfloat16 g_Xlo [(size_t)NMAX * 128];
__device__ __align__(16) __nv_bfloat16 g_X2hi[(size_t)NMAX * 128];
__device__ __align__(16) __nv_bfloat16 g_X2lo[(size_t)NMAX * 128];
__device__ __align__(16) __nv_bfloat16 g_W1hi[128 * 128];
__device__ __align__(16) __nv_bfloat16 g_W1lo[128 * 128];
__device__ __align__(16) __nv_bfloat16 g_W2hi[128 * 64];
__device__ __align__(16) __nv_bfloat16 g_W2lo[128 * 64];

__device__ __align__(16) __half g_G1h[(size_t)NMAX * 128];   // fp16 layer-1 msgs
__device__ __align__(16) float  g_G2 [(size_t)NMAX * 64];

// --------------------------- asm helpers -----------------------------------
__device__ __forceinline__ uint32_t smem_u32(const void* p) {
    uint32_t a;
    asm("{ .reg .u64 t; cvta.to.shared.u64 t, %1; cvt.u32.u64 %0, t; }"
        : "=r"(a) : "l"(p));
    return a;
}
#define CP_ASYNC16(dst, src, sz) \
    asm volatile("cp.async.cg.shared.global [%0], [%1], 16, %2;" \
                 :: "r"(dst), "l"(src), "r"(sz) : "memory")
#define CP_COMMIT() asm volatile("cp.async.commit_group;" ::: "memory")
#define CP_WAIT0()  asm volatile("cp.async.wait_group 0;" ::: "memory")
#define CP_WAIT1()  asm volatile("cp.async.wait_group 1;" ::: "memory")

#define LDSM_X4(r0, r1, r2, r3, addr) \
    asm volatile("ldmatrix.sync.aligned.m8n8.x4.shared.b16 {%0,%1,%2,%3}, [%4];" \
                 : "=r"(r0), "=r"(r1), "=r"(r2), "=r"(r3) : "r"(addr))
#define LDSM_X4_T(r0, r1, r2, r3, addr) \
    asm volatile("ldmatrix.sync.aligned.m8n8.x4.trans.shared.b16 {%0,%1,%2,%3}, [%4];" \
                 : "=r"(r0), "=r"(r1), "=r"(r2), "=r"(r3) : "r"(addr))

__device__ __forceinline__ void mma_bf16(float* c, const uint32_t* a,
                                         uint32_t b0, uint32_t b1) {
    asm volatile(
        "mma.sync.aligned.m16n8k16.row.col.f32.bf16.bf16.f32 "
        "{%0,%1,%2,%3}, {%4,%5,%6,%7}, {%8,%9}, {%0,%1,%2,%3};"
        : "+f"(c[0]), "+f"(c[1]), "+f"(c[2]), "+f"(c[3])
        : "r"(a[0]), "r"(a[1]), "r"(a[2]), "r"(a[3]), "r"(b0), "r"(b1));
}

__device__ __forceinline__ void split_bf16(float v, __nv_bfloat16& h, __nv_bfloat16& l) {
    h = __float2bfloat16(v);
    l = __float2bfloat16(v - __bfloat162float(h));
}

// ---------------------------------------------------------------------------
// fused preconvert: zero counts/cursors + X->bf16 hi/lo + W1,W2->bf16 hi/lo
// ---------------------------------------------------------------------------
__global__ void pre_kernel(const float* __restrict__ X,
                           const float* __restrict__ W1,
                           const float* __restrict__ W2, int nrows) {
    int i = blockIdx.x * blockDim.x + threadIdx.x;

    if (i < nrows * 32) {                       // X: float4 granules
        float4 v = reinterpret_cast<const float4*>(X)[i];
        __nv_bfloat16 hx, hy, hz, hw, lx, ly, lz, lw;
        split_bf16(v.x, hx, lx); split_bf16(v.y, hy, ly);
        split_bf16(v.z, hz, lz); split_bf16(v.w, hw, lw);
        uint2 h = make_uint2(
            (uint32_t)__bfloat16_as_ushort(hx) | ((uint32_t)__bfloat16_as_ushort(hy) << 16),
            (uint32_t)__bfloat16_as_ushort(hz) | ((uint32_t)__bfloat16_as_ushort(hw) << 16));
        uint2 l = make_uint2(
            (uint32_t)__bfloat16_as_ushort(lx) | ((uint32_t)__bfloat16_as_ushort(ly) << 16),
            (uint32_t)__bfloat16_as_ushort(lz) | ((uint32_t)__bfloat16_as_ushort(lw) << 16));
        reinterpret_cast<uint2*>(g_Xhi)[i] = h;
        reinterpret_cast<uint2*>(g_Xlo)[i] = l;
    }
    if (i < NMAX) { g_cnt[i] = 0; g_cursor[i] = 0; }
    if (i < 128 * 128) {
        __nv_bfloat16 h, l;
        split_bf16(W1[i], h, l);
        g_W1hi[i] = h; g_W1lo[i] = l;
    }
    if (i < 128 * 64) {
        __nv_bfloat16 h, l;
        split_bf16(W2[i], h, l);
        g_W2hi[i] = h; g_W2lo[i] = l;
    }
}

// ---------------------------------------------------------------------------
// CSR build: hist -> 3-phase scan (A: per-block, B: block totals, C: add+dinv)
// ---------------------------------------------------------------------------
__global__ void hist_kernel(const int* __restrict__ dst, int E) {
    int e = blockIdx.x * blockDim.x + threadIdx.x;
    if (e < E) atomicAdd(&g_cnt[dst[e]], 1);
}

__global__ __launch_bounds__(1024) void scanA_kernel(int n) {
    __shared__ int wsums[32];
    int tid = threadIdx.x, lane = tid & 31, wid = tid >> 5;
    int i = blockIdx.x * 1024 + tid;
    int v = (i < n) ? g_cnt[i] : 0;
    int x = v;
#pragma unroll
    for (int d = 1; d < 32; d <<= 1) {
        int y = __shfl_up_sync(0xffffffffu, x, d);
        if (lane >= d) x += y;
    }
    if (lane == 31) wsums[wid] = x;
    __syncthreads();
    if (wid == 0) {
        int s = wsums[lane];
#pragma unroll
        for (int d = 1; d < 32; d <<= 1) {
            int y = __shfl_up_sync(0xffffffffu, s, d);
            if (lane >= d) s += y;
        }
        wsums[lane] = s;
    }
    __syncthreads();
    int woff = wid ? wsums[wid - 1] : 0;
    if (i < n) g_rowstart[i] = woff + x - v;        // block-local exclusive
    if (tid == 1023) g_btot[blockIdx.x] = wsums[31];
}

__global__ void scanB_kernel(int nb, int n) {       // one block, 64 threads
    __shared__ int s[64];
    int t = threadIdx.x;
    int v = (t < nb) ? g_btot[t] : 0;
    s[t] = v;
    __syncthreads();
#pragma unroll
    for (int d = 1; d < 64; d <<= 1) {
        int y = (t >= d) ? s[t - d] : 0;
        __syncthreads();
        s[t] += y;
        __syncthreads();
    }
    if (t < nb) g_boff[t] = s[t] - v;               // exclusive
    if (t == nb - 1) g_rowstart[n] = s[t];          // grand total
}

__global__ void scanC_kernel(int n) {               // add offsets + dinv
    int i = blockIdx.x * blockDim.x + threadIdx.x;
    if (i < n) {
        g_rowstart[i] += g_boff[i >> 10];
        g_dinv[i] = rsqrtf((float)g_cnt[i] + 1.0f); // +1 self-loop
    }
}

__global__ void fill_kernel(const int* __restrict__ src,
                            const int* __restrict__ dst, int E) {
    int e = blockIdx.x * blockDim.x + threadIdx.x;
    if (e < E) {
        int d = dst[e];
        int p = g_rowstart[d] + atomicAdd(&g_cursor[d], 1);
        g_col[p] = src[e];
    }
}

// ---------------------------------------------------------------------------
// cp.async pipelined HMMA GEMM:  G = dinv[row] .* (A @ W)
// CTA 128 rows x N cols. 8 warps: warp = (wid&3)*32 rows x (wid>>2)*(N/2) cols.
// K=128 as 8 chunks of 16, double-buffered. 3-pass bf16 split.
// N=128 -> stores fp16 to g_G1h;  N=64 -> stores fp32 to g_G2.
// ---------------------------------------------------------------------------
template <int N>
__global__ __launch_bounds__(256, 2) void gemm_pipe_kernel(int nrows)
{
    extern __shared__ char smem[];
    const __nv_bfloat16* __restrict__ Ahi = (N == 128) ? g_Xhi  : g_X2hi;
    const __nv_bfloat16* __restrict__ Alo = (N == 128) ? g_Xlo  : g_X2lo;
    const __nv_bfloat16* __restrict__ Bhi = (N == 128) ? g_W1hi : g_W2hi;
    const __nv_bfloat16* __restrict__ Blo = (N == 128) ? g_W1lo : g_W2lo;

    constexpr int SBb  = (N + 8) * 2;
    constexpr int AH_O = 0;
    constexpr int AL_O = 128 * 48;
    constexpr int BH_O = 2 * 128 * 48;
    constexpr int BSZ  = 16 * SBb;
    constexpr int BL_O = BH_O + BSZ;
    constexpr int BUF  = BH_O + 2 * BSZ;
    constexpr int BPR  = N / 8;
    constexpr int BOPS = 16 * BPR * 2;
    constexpr int CW   = N / 2;
    constexpr int NG   = CW / 16;

    const int tid  = threadIdx.x;
    const int wid  = tid >> 5;
    const int lane = tid & 31;
    const int row0 = blockIdx.x * 128;
    const uint32_t sb = smem_u32(smem);

    auto issue = [&](int c) {
        const uint32_t base = sb + (uint32_t)(c & 1) * BUF;
#pragma unroll
        for (int it = 0; it < 2; it++) {
            int i   = tid + it * 256;
            int mat = i >> 8;
            int idx = i & 255;
            int r   = idx >> 1;
            int j   = idx & 1;
            uint32_t dst = base + (mat ? AL_O : AH_O) + r * 48 + j * 16;
            const __nv_bfloat16* srcb = mat ? Alo : Ahi;
            int row = row0 + r;
            int srow = (row < nrows) ? row : 0;
            const char* src = (const char*)srcb
                            + (size_t)srow * 256 + c * 32 + j * 16;
            uint32_t sz = (row < nrows) ? 16u : 0u;
            CP_ASYNC16(dst, src, sz);
        }
#pragma unroll
        for (int it = 0; it < BOPS / 256; it++) {
            int i   = tid + it * 256;
            int mat = i >= BOPS / 2;
            int idx = mat ? (i - BOPS / 2) : i;
            int r   = idx / BPR;
            int j   = idx % BPR;
            uint32_t dst = base + (mat ? BL_O : BH_O) + r * SBb + j * 16;
            const __nv_bfloat16* srcb = mat ? Blo : Bhi;
            const char* src = (const char*)srcb + (size_t)(c * 16 + r) * N * 2 + j * 16;
            CP_ASYNC16(dst, src, 16u);
        }
    };

    const int wrow = (wid & 3) * 32;
    const int col0 = (wid >> 2) * CW;

    float cfrag[2][CW / 8][4];
#pragma unroll
    for (int mi = 0; mi < 2; mi++)
#pragma unroll
        for (int t = 0; t < CW / 8; t++)
#pragma unroll
            for (int j = 0; j < 4; j++) cfrag[mi][t][j] = 0.0f;

    issue(0); CP_COMMIT();
    issue(1); CP_COMMIT();

    for (int c = 0; c < 8; c++) {
        if (c == 7) { CP_WAIT0(); } else { CP_WAIT1(); }
        __syncthreads();

        const uint32_t base = sb + (uint32_t)(c & 1) * BUF;
        uint32_t a0 = base + AH_O + (wrow + (lane & 15)) * 48 + (lane >> 4) * 16;
        uint32_t a1 = a0 + 16 * 48;
        uint32_t ah0[4], ah1[4], al0[4], al1[4];
        LDSM_X4(ah0[0], ah0[1], ah0[2], ah0[3], a0);
        LDSM_X4(ah1[0], ah1[1], ah1[2], ah1[3], a1);
        LDSM_X4(al0[0], al0[1], al0[2], al0[3], a0 + AL_O);
        LDSM_X4(al1[0], al1[1], al1[2], al1[3], a1 + AL_O);

#pragma unroll
        for (int ng = 0; ng < NG; ng++) {
            uint32_t bo = base + BH_O + (lane & 15) * SBb + (lane >> 4) * 16
                        + (col0 + ng * 16) * 2;
            uint32_t bh[4], bl[4];
            LDSM_X4_T(bh[0], bh[1], bh[2], bh[3], bo);
            LDSM_X4_T(bl[0], bl[1], bl[2], bl[3], bo + BSZ);

            mma_bf16(cfrag[0][2 * ng],     ah0, bh[0], bh[1]);
            mma_bf16(cfrag[0][2 * ng + 1], ah0, bh[2], bh[3]);
            mma_bf16(cfrag[1][2 * ng],     ah1, bh[0], bh[1]);
            mma_bf16(cfrag[1][2 * ng + 1], ah1, bh[2], bh[3]);
            mma_bf16(cfrag[0][2 * ng],     ah0, bl[0], bl[1]);
            mma_bf16(cfrag[0][2 * ng + 1], ah0, bl[2], bl[3]);
            mma_bf16(cfrag[1][2 * ng],     ah1, bl[0], bl[1]);
            mma_bf16(cfrag[1][2 * ng + 1], ah1, bl[2], bl[3]);
            mma_bf16(cfrag[0][2 * ng],     al0, bh[0], bh[1]);
            mma_bf16(cfrag[0][2 * ng + 1], al0, bh[2], bh[3]);
            mma_bf16(cfrag[1][2 * ng],     al1, bh[0], bh[1]);
            mma_bf16(cfrag[1][2 * ng + 1], al1, bh[2], bh[3]);
        }
        __syncthreads();
        if (c < 6) { issue(c + 2); CP_COMMIT(); }
    }

    // ---- epilogue: dinv scale; fp16 store (N=128) / fp32 store (N=64) ----
#pragma unroll
    for (int mi = 0; mi < 2; mi++) {
        int rA = row0 + wrow + mi * 16 + (lane >> 2);
        int rB = rA + 8;
        float sA = (rA < nrows) ? g_dinv[rA] : 0.0f;
        float sB = (rB < nrows) ? g_dinv[rB] : 0.0f;
#pragma unroll
        for (int t = 0; t < CW / 8; t++) {
            int col = col0 + t * 8 + (lane & 3) * 2;
            if (N == 128) {
                if (rA < nrows)
                    *(__half2*)(g_G1h + (size_t)rA * 128 + col) =
                        __floats2half2_rn(cfrag[mi][t][0] * sA, cfrag[mi][t][1] * sA);
                if (rB < nrows)
                    *(__half2*)(g_G1h + (size_t)rB * 128 + col) =
                        __floats2half2_rn(cfrag[mi][t][2] * sB, cfrag[mi][t][3] * sB);
            } else {
                if (rA < nrows)
                    *(float2*)(g_G2 + (size_t)rA * 64 + col) =
                        make_float2(cfrag[mi][t][0] * sA, cfrag[mi][t][1] * sA);
                if (rB < nrows)
                    *(float2*)(g_G2 + (size_t)rB * 64 + col) =
                        make_float2(cfrag[mi][t][2] * sB, cfrag[mi][t][3] * sB);
            }
        }
    }
}

// ---------------------------------------------------------------------------
// fused CSR gather + finalize
// layer 1 (fp16 G1): out = relu(dinv[d]*(G1[d]+sum G1[src]) + b1) -> X2hi/lo
// warp per row; lane covers 4 cols (uint2 = 2 x half2)
// ---------------------------------------------------------------------------
__global__ __launch_bounds__(256) void gather1_kernel(
    const float* __restrict__ b1, int n)
{
    int wid  = threadIdx.x >> 5;
    int lane = threadIdx.x & 31;
    int row  = blockIdx.x * 8 + wid;
    if (row >= n) return;

    const uint2* G = reinterpret_cast<const uint2*>(g_G1h);   // 32 uint2/row
    int s0 = g_rowstart[row], s1 = g_rowstart[row + 1];

    float4 acc[4];
    {
        uint2 u = G[(size_t)row * 32 + lane];                 // self-loop
        float2 fa = __half22float2(*(const __half2*)&u.x);
        float2 fb = __half22float2(*(const __half2*)&u.y);
        acc[0] = make_float4(fa.x, fa.y, fb.x, fb.y);
        acc[1] = make_float4(0.f, 0.f, 0.f, 0.f);
        acc[2] = make_float4(0.f, 0.f, 0.f, 0.f);
        acc[3] = make_float4(0.f, 0.f, 0.f, 0.f);
    }

    int e = s0;
    for (; e + 4 <= s1; e += 4) {
        int i0 = g_col[e], i1 = g_col[e + 1], i2 = g_col[e + 2], i3 = g_col[e + 3];
        uint2 u0 = G[(size_t)i0 * 32 + lane];
        uint2 u1 = G[(size_t)i1 * 32 + lane];
        uint2 u2 = G[(size_t)i2 * 32 + lane];
        uint2 u3 = G[(size_t)i3 * 32 + lane];
#pragma unroll
        for (int q = 0; q < 4; q++) {
            uint2 u = (q == 0) ? u0 : (q == 1) ? u1 : (q == 2) ? u2 : u3;
            float2 fa = __half22float2(*(const __half2*)&u.x);
            float2 fb = __half22float2(*(const __half2*)&u.y);
            acc[q].x += fa.x; acc[q].y += fa.y; acc[q].z += fb.x; acc[q].w += fb.y;
        }
    }
    for (; e < s1; e++) {
        uint2 u = G[(size_t)g_col[e] * 32 + lane];
        float2 fa = __half22float2(*(const __half2*)&u.x);
        float2 fb = __half22float2(*(const __half2*)&u.y);
        acc[0].x += fa.x; acc[0].y += fa.y; acc[0].z += fb.x; acc[0].w += fb.y;
    }
    float4 a = make_float4(acc[0].x + acc[1].x + acc[2].x + acc[3].x,
                           acc[0].y + acc[1].y + acc[2].y + acc[3].y,
                           acc[0].z + acc[1].z + acc[2].z + acc[3].z,
                           acc[0].w + acc[1].w + acc[2].w + acc[3].w);

    float sc = g_dinv[row];
    float4 bv = reinterpret_cast<const float4*>(b1)[lane];
    float vx = fmaxf(sc * a.x + bv.x, 0.0f);
    float vy = fmaxf(sc * a.y + bv.y, 0.0f);
    float vz = fmaxf(sc * a.z + bv.z, 0.0f);
    float vw = fmaxf(sc * a.w + bv.w, 0.0f);

    __nv_bfloat16 hx, hy, hz, hw, lx, ly, lz, lw;
    split_bf16(vx, hx, lx); split_bf16(vy, hy, ly);
    split_bf16(vz, hz, lz); split_bf16(vw, hw, lw);
    uint2 h = make_uint2(
        (uint32_t)__bfloat16_as_ushort(hx) | ((uint32_t)__bfloat16_as_ushort(hy) << 16),
        (uint32_t)__bfloat16_as_ushort(hz) | ((uint32_t)__bfloat16_as_ushort(hw) << 16));
    uint2 l = make_uint2(
        (uint32_t)__bfloat16_as_ushort(lx) | ((uint32_t)__bfloat16_as_ushort(ly) << 16),
        (uint32_t)__bfloat16_as_ushort(lz) | ((uint32_t)__bfloat16_as_ushort(lw) << 16));
    size_t oi = (size_t)row * 32 + lane;
    reinterpret_cast<uint2*>(g_X2hi)[oi] = h;
    reinterpret_cast<uint2*>(g_X2lo)[oi] = l;
}

// layer 2 (fp32 G2): out = dinv[d]*(G2[d]+sum G2[src]) + b2
__global__ __launch_bounds__(256) void gather2_kernel(
    float* __restrict__ out, const float* __restrict__ b2, int n)
{
    int wid  = threadIdx.x >> 5;
    int lane = threadIdx.x & 31;
    int row  = blockIdx.x * 8 + wid;
    if (row >= n) return;

    const float2* G = reinterpret_cast<const float2*>(g_G2);
    int s0 = g_rowstart[row], s1 = g_rowstart[row + 1];

    float2 acc[4];
    acc[0] = G[(size_t)row * 32 + lane];
    acc[1] = make_float2(0.f, 0.f);
    acc[2] = make_float2(0.f, 0.f);
    acc[3] = make_float2(0.f, 0.f);

    int e = s0;
    for (; e + 4 <= s1; e += 4) {
        int i0 = g_col[e], i1 = g_col[e + 1], i2 = g_col[e + 2], i3 = g_col[e + 3];
        float2 v0 = G[(size_t)i0 * 32 + lane];
        float2 v1 = G[(size_t)i1 * 32 + lane];
        float2 v2 = G[(size_t)i2 * 32 + lane];
        float2 v3 = G[(size_t)i3 * 32 + lane];
        acc[0].x += v0.x; acc[0].y += v0.y;
        acc[1].x += v1.x; acc[1].y += v1.y;
        acc[2].x += v2.x; acc[2].y += v2.y;
        acc[3].x += v3.x; acc[3].y += v3.y;
    }
    for (; e < s1; e++) {
        float2 v = G[(size_t)g_col[e] * 32 + lane];
        acc[0].x += v.x; acc[0].y += v.y;
    }
    float2 a = make_float2(acc[0].x + acc[1].x + acc[2].x + acc[3].x,
                           acc[0].y + acc[1].y + acc[2].y + acc[3].y);

    float sc = g_dinv[row];
    float2 bv = reinterpret_cast<const float2*>(b2)[lane];
    reinterpret_cast<float2*>(out)[(size_t)row * 32 + lane] =
        make_float2(sc * a.x + bv.x, sc * a.y + bv.y);
}

// ---------------------------------------------------------------------------
// launch
// ---------------------------------------------------------------------------
extern "C" void kernel_launch(void* const* d_in, const int* in_sizes, int n_in,
                              void* d_out, int out_size)
{
    const float* x  = (const float*)d_in[0];
    const int*   ei = (const int*)  d_in[1];
    const float* W1 = (const float*)d_in[2];
    const float* b1 = (const float*)d_in[3];
    const float* W2 = (const float*)d_in[4];
    const float* b2 = (const float*)d_in[5];

    const int nrows = in_sizes[0] / 128;   // 50000
    const int E     = in_sizes[1] / 2;     // 625000
    const int* src = ei;
    const int* dst = ei + E;

    constexpr int SMEM128 = 2 * (2 * 128 * 48 + 2 * 16 * (128 + 8) * 2);  // 41984
    constexpr int SMEM64  = 2 * (2 * 128 * 48 + 2 * 16 * (64 + 8) * 2);   // 33792

    const int nb = (nrows + 1023) / 1024;   // 49

    // fused preconvert (covers X granules = nrows*32 items, largest range)
    pre_kernel<<<(nrows * 32 + 255) / 256, 256>>>(x, W1, W2, nrows);

    // CSR build
    hist_kernel<<<(E + 255) / 256, 256>>>(dst, E);
    scanA_kernel<<<nb, 1024>>>(nrows);
    scanB_kernel<<<1, 64>>>(nb, nrows);
    scanC_kernel<<<(nrows + 255) / 256, 256>>>(nrows);
    fill_kernel<<<(E + 255) / 256, 256>>>(src, dst, E);

    const int gemm_blocks   = (nrows + 127) / 128;  // 391
    const int gather_blocks = (nrows + 7) / 8;      // 6250

    // ---- layer 1 ----
    gemm_pipe_kernel<128><<<gemm_blocks, 256, SMEM128>>>(nrows);
    gather1_kernel<<<gather_blocks, 256>>>(b1, nrows);

    // ---- layer 2 ----
    gemm_pipe_kernel<64><<<gemm_blocks, 256, SMEM64>>>(nrows);
    gather2_kernel<<<gather_blocks, 256>>>((float*)d_out, b2, nrows);
}